// round 11
// baseline (speedup 1.0000x reference)
#include <cuda_runtime.h>
#include <math_constants.h>
#include <cstdint>

#define NL 16384
#define NR 16384
#define CH 256
#define KNN 16

// ---------------- scratch (device globals; no allocation) ----------------
__device__ float4 g_refpack[NR];
__device__ int    g_idx[NL * KNN];
__device__ float  g_refK0[NR * CH];
__device__ float  g_refV0[NR * CH];
__device__ float  g_refK1[NR * CH];
__device__ float  g_refV1[NR * CH];
__device__ float  g_Q[NL * CH];
__device__ float  g_out0[NL * CH];
__device__ float  g_out1[NL * CH];
__device__ float  g_t[NL * CH];
__device__ float  g_u[NL * CH];
__device__ float  g_Wp[4][3][CH];   // pos_w @ {k0,v0,k1,v1}_w
__device__ float  g_cb[4][CH];      // pos_b @ w + b
__device__ float  g_ps[64 * CH];
__device__ float  g_pq[64 * CH];
__device__ float  g_scale[CH];
__device__ float  g_shift[CH];

// ---------------- pack refs: (x,y,z,|r|^2) ----------------
__global__ void pack_kernel(const float* __restrict__ refC) {
    int i = blockIdx.x * 256 + threadIdx.x;
    float x = refC[i * 3 + 0], y = refC[i * 3 + 1], z = refC[i * 3 + 2];
    g_refpack[i] = make_float4(x, y, z, x * x + y * y + z * z);
}

// ---------------- KNN: 64 queries/block, 4 stripes/query ----------------
// Early-exit insert: all register indices static; exits at the found slot.
// Tie order: v[j-1] <= cv places an equal value AFTER the existing one, i.e.
// ascending index for equal distances -> identical to stable top_k.
__device__ __forceinline__ void topk_insert(float (&v)[KNN], int (&id)[KNN], float cv, int ci) {
    #pragma unroll
    for (int j = KNN - 1; j > 0; --j) {
        if (v[j - 1] <= cv) { v[j] = cv; id[j] = ci; return; }
        v[j] = v[j - 1]; id[j] = id[j - 1];
    }
    v[0] = cv; id[0] = ci;
}

__global__ __launch_bounds__(256) void knn_kernel(const float* __restrict__ lossyC) {
    __shared__ float4 sm[512];              // phase tile: 512 refs
    __shared__ float  s_val[4][64][KNN];    // per-stripe partial top-16 values
    __shared__ int    s_idx[4][64][KNN];    // per-stripe partial top-16 indices

    const int ql     = threadIdx.x & 63;    // local query 0..63
    const int stripe = threadIdx.x >> 6;    // 0..3
    const int q      = blockIdx.x * 64 + ql;

    const float qx2 = -2.0f * lossyC[q * 3 + 0];
    const float qy2 = -2.0f * lossyC[q * 3 + 1];
    const float qz2 = -2.0f * lossyC[q * 3 + 2];

    float v[KNN]; int id[KNN];
    #pragma unroll
    for (int j = 0; j < KNN; j++) { v[j] = CUDART_INF_F; id[j] = 0; }

    // Stripe s scans [m*512 + s*128, +128) per phase: per-stripe global indices
    // strictly increase across phases -> insertion keeps top_k tie semantics.
    for (int m = 0; m < 32; m++) {
        __syncthreads();
        int base = m * 512;
        sm[threadIdx.x]       = g_refpack[base + threadIdx.x];
        sm[threadIdx.x + 256] = g_refpack[base + threadIdx.x + 256];
        __syncthreads();

        const float4* my = &sm[stripe * 128];
        int gbase = base + stripe * 128;
        for (int r = 0; r < 128; r += 4) {
            float4 a = my[r + 0], b = my[r + 1], c = my[r + 2], d = my[r + 3];
            // val = |r|^2 - 2 q.r : exact fp32 integers -> exact tie semantics
            float c0 = fmaf(a.x, qx2, fmaf(a.y, qy2, fmaf(a.z, qz2, a.w)));
            float c1 = fmaf(b.x, qx2, fmaf(b.y, qy2, fmaf(b.z, qz2, b.w)));
            float c2 = fmaf(c.x, qx2, fmaf(c.y, qy2, fmaf(c.z, qz2, c.w)));
            float c3 = fmaf(d.x, qx2, fmaf(d.y, qy2, fmaf(d.z, qz2, d.w)));
            if (c0 < v[KNN - 1]) topk_insert(v, id, c0, gbase + r + 0);
            if (c1 < v[KNN - 1]) topk_insert(v, id, c1, gbase + r + 1);
            if (c2 < v[KNN - 1]) topk_insert(v, id, c2, gbase + r + 2);
            if (c3 < v[KNN - 1]) topk_insert(v, id, c3, gbase + r + 3);
        }
    }

    #pragma unroll
    for (int j = 0; j < KNN; j++) {
        s_val[stripe][ql][j] = v[j];
        s_idx[stripe][ql][j] = id[j];
    }
    __syncthreads();

    // 4-way merge by (val, idx) lexicographic -> exact top_k order.
    if (threadIdx.x < 64) {
        int p[4] = {0, 0, 0, 0};
        #pragma unroll
        for (int j = 0; j < KNN; j++) {
            float bv = s_val[0][threadIdx.x][p[0]];
            int   bi = s_idx[0][threadIdx.x][p[0]];
            int   bs = 0;
            #pragma unroll
            for (int s = 1; s < 4; s++) {
                float cv = s_val[s][threadIdx.x][p[s]];
                int   ci = s_idx[s][threadIdx.x][p[s]];
                if (cv < bv || (cv == bv && ci < bi)) { bv = cv; bi = ci; bs = s; }
            }
            g_idx[(blockIdx.x * 64 + threadIdx.x) * KNN + j] = bi;
            p[bs]++;
        }
    }
}

// ---------------- tiny precompute: Wp = pos_w @ w, cb = pos_b @ w + b ----------------
__global__ void precompute_kernel(const float* __restrict__ p0w, const float* __restrict__ p0b,
                                  const float* __restrict__ p1w, const float* __restrict__ p1b,
                                  const float* __restrict__ k0w, const float* __restrict__ k0b,
                                  const float* __restrict__ v0w, const float* __restrict__ v0b,
                                  const float* __restrict__ k1w, const float* __restrict__ k1b,
                                  const float* __restrict__ v1w, const float* __restrict__ v1b) {
    int c = threadIdx.x;
    int s = blockIdx.x;
    const float* pw[4] = {p0w, p0w, p1w, p1w};
    const float* pb[4] = {p0b, p0b, p1b, p1b};
    const float* w [4] = {k0w, v0w, k1w, v1w};
    const float* bb[4] = {k0b, v0b, k1b, v1b};
    for (int r = 0; r < 3; r++) {
        float acc = 0.0f;
        for (int m = 0; m < CH; m++) acc = fmaf(pw[s][r * CH + m], w[s][m * CH + c], acc);
        g_Wp[s][r][c] = acc;
    }
    float acc = 0.0f;
    for (int m = 0; m < CH; m++) acc = fmaf(pb[s][m], w[s][m * CH + c], acc);
    g_cb[s][c] = acc + bb[s][c];
}

// ---------------- fp32 GEMM with cp.async double-buffering ----------------
#define BM 128
#define BN 128
#define BK 16

__device__ __forceinline__ void cp_async16(uint32_t s, const void* g) {
    asm volatile("cp.async.cg.shared.global [%0], [%1], 16;\n" :: "r"(s), "l"(g));
}
__device__ __forceinline__ void cp_commit() { asm volatile("cp.async.commit_group;\n" ::: "memory"); }
__device__ __forceinline__ void cp_wait0()  { asm volatile("cp.async.wait_group 0;\n" ::: "memory"); }

__global__ __launch_bounds__(256, 2) void gemm_kernel(const float* __restrict__ A,
                                                      const float* __restrict__ B,
                                                      const float* __restrict__ bias,
                                                      float* __restrict__ Cout) {
    // As4[buf][k4][row] holds A[bm+row][kk + k4*4 .. +3] as one float4 (no transpose).
    // Bs4[buf][k][c4]   holds B[kk+k][bn + c4*4 .. +3].
    __shared__ float4 As4[2][BK / 4][BM];
    __shared__ float4 Bs4[2][BK][BN / 4];

    const int tid = threadIdx.x;
    const int bm = blockIdx.x * BM;
    const int bn = blockIdx.y * BN;
    const int tx = tid & 15;
    const int ty = tid >> 4;

    auto prefetch = [&](int kk, int buf) {
        #pragma unroll
        for (int u = 0; u < 2; u++) {
            int f = tid + u * 256;
            int row = f >> 2, k4 = f & 3;
            cp_async16((uint32_t)__cvta_generic_to_shared(&As4[buf][k4][row]),
                       A + (size_t)(bm + row) * CH + kk + k4 * 4);
            int kr = f >> 5, c4 = f & 31;
            cp_async16((uint32_t)__cvta_generic_to_shared(&Bs4[buf][kr][c4]),
                       B + (size_t)(kk + kr) * CH + bn + c4 * 4);
        }
        cp_commit();
    };

    float acc[8][8];
    #pragma unroll
    for (int i = 0; i < 8; i++)
        #pragma unroll
        for (int j = 0; j < 8; j++) acc[i][j] = 0.0f;

    prefetch(0, 0);

    #pragma unroll 1
    for (int t = 0; t < CH / BK; t++) {
        cp_wait0();
        __syncthreads();          // tile t visible to all; everyone done with tile t-1
        if (t + 1 < CH / BK) prefetch((t + 1) * BK, (t + 1) & 1);
        const int buf = t & 1;

        #pragma unroll
        for (int k4 = 0; k4 < BK / 4; k4++) {
            float4 av[8];
            #pragma unroll
            for (int i = 0; i < 4; i++) {
                av[i]     = As4[buf][k4][ty * 4 + i];
                av[i + 4] = As4[buf][k4][64 + ty * 4 + i];
            }
            #pragma unroll
            for (int k2 = 0; k2 < 4; k2++) {
                float4 b0 = Bs4[buf][k4 * 4 + k2][tx];
                float4 b1 = Bs4[buf][k4 * 4 + k2][tx + 16];
                float b[8] = {b0.x, b0.y, b0.z, b0.w, b1.x, b1.y, b1.z, b1.w};
                float a[8];
                #pragma unroll
                for (int i = 0; i < 8; i++) {
                    a[i] = (k2 == 0) ? av[i].x : (k2 == 1) ? av[i].y : (k2 == 2) ? av[i].z : av[i].w;
                }
                #pragma unroll
                for (int i = 0; i < 8; i++)
                    #pragma unroll
                    for (int j = 0; j < 8; j++)
                        acc[i][j] = fmaf(a[i], b[j], acc[i][j]);
            }
        }
        __syncthreads();
    }

    #pragma unroll
    for (int i = 0; i < 8; i++) {
        int row = bm + ((i < 4) ? (ty * 4 + i) : (64 + ty * 4 + i - 4));
        #pragma unroll
        for (int jh = 0; jh < 2; jh++) {
            int col = bn + jh * 64 + tx * 4;
            float4 o;
            o.x = acc[i][jh * 4 + 0]; o.y = acc[i][jh * 4 + 1];
            o.z = acc[i][jh * 4 + 2]; o.w = acc[i][jh * 4 + 3];
            if (bias) {
                o.x += bias[col + 0]; o.y += bias[col + 1];
                o.z += bias[col + 2]; o.w += bias[col + 3];
            }
            *(float4*)(Cout + (size_t)row * CH + col) = o;
        }
    }
}

// ---------------- attention: one query per warp, float4 gathers ----------------
// lane -> channels c = lane*8 + j, j in 0..7 (two float4 per row per lane)
__global__ __launch_bounds__(256) void attn_kernel(const float* __restrict__ Q,
                                                   const float* __restrict__ lossyC,
                                                   float* __restrict__ out,
                                                   int layer) {
    const float* __restrict__ refK = layer ? g_refK1 : g_refK0;
    const float* __restrict__ refV = layer ? g_refV1 : g_refV0;
    const float* __restrict__ Wpk  = &g_Wp[2 * layer][0][0];
    const float* __restrict__ cbk  = g_cb[2 * layer];
    const float* __restrict__ Wpv  = &g_Wp[2 * layer + 1][0][0];
    const float* __restrict__ cbv  = g_cb[2 * layer + 1];

    const int lane = threadIdx.x & 31;
    const int warp = threadIdx.x >> 5;
    const int n = blockIdx.x * 8 + warp;    // grid = NL/8 = 2048
    const int c0 = lane * 8;

    float wpk[3][8], cbkr[8];
    #pragma unroll
    for (int j = 0; j < 8; j++) {
        #pragma unroll
        for (int r = 0; r < 3; r++) wpk[r][j] = Wpk[r * CH + c0 + j];
        cbkr[j] = cbk[c0 + j];
    }

    const float qx = lossyC[n * 3 + 0], qy = lossyC[n * 3 + 1], qz = lossyC[n * 3 + 2];
    float q[8];
    {
        const float4* qp = (const float4*)(Q + (size_t)n * CH + c0);
        float4 qa = qp[0], qb = qp[1];
        q[0] = qa.x; q[1] = qa.y; q[2] = qa.z; q[3] = qa.w;
        q[4] = qb.x; q[5] = qb.y; q[6] = qb.z; q[7] = qb.w;
    }

    int nb[KNN];
    #pragma unroll
    for (int k = 0; k < KNN; k++) nb[k] = g_idx[n * KNN + k];

    float lgt[KNN];
    #pragma unroll
    for (int k = 0; k < KNN; k++) {
        int i = nb[k];
        float4 rp = g_refpack[i];
        float rx = qx - rp.x, ry = qy - rp.y, rz = qz - rp.z;
        const float4* kp = (const float4*)(refK + (size_t)i * CH + c0);
        float4 ka = kp[0], kb = kp[1];
        float km[8] = {ka.x, ka.y, ka.z, ka.w, kb.x, kb.y, kb.z, kb.w};
        float dot = 0.0f;
        #pragma unroll
        for (int j = 0; j < 8; j++) {
            float t = km[j];
            t = fmaf(rx, wpk[0][j], t);
            t = fmaf(ry, wpk[1][j], t);
            t = fmaf(rz, wpk[2][j], t);
            t += cbkr[j];
            dot = fmaf(t, q[j], dot);
        }
        #pragma unroll
        for (int o = 16; o > 0; o >>= 1) dot += __shfl_xor_sync(0xffffffffu, dot, o);
        lgt[k] = dot * 0.0625f;   // / sqrt(256)
    }
    float mx = lgt[0];
    #pragma unroll
    for (int k = 1; k < KNN; k++) mx = fmaxf(mx, lgt[k]);
    float s = 0.0f;
    #pragma unroll
    for (int k = 0; k < KNN; k++) { float e = __expf(lgt[k] - mx); lgt[k] = e; s += e; }
    float inv = 1.0f / s;

    float wpv[3][8], cbvr[8];
    #pragma unroll
    for (int j = 0; j < 8; j++) {
        #pragma unroll
        for (int r = 0; r < 3; r++) wpv[r][j] = Wpv[r * CH + c0 + j];
        cbvr[j] = cbv[c0 + j];
    }

    float acc[8];
    #pragma unroll
    for (int j = 0; j < 8; j++) acc[j] = 0.0f;
    #pragma unroll
    for (int k = 0; k < KNN; k++) {
        int i = nb[k];
        float4 rp = g_refpack[i];
        float rx = qx - rp.x, ry = qy - rp.y, rz = qz - rp.z;
        float w = lgt[k] * inv;
        const float4* vp = (const float4*)(refV + (size_t)i * CH + c0);
        float4 va = vp[0], vb = vp[1];
        float vm[8] = {va.x, va.y, va.z, va.w, vb.x, vb.y, vb.z, vb.w};
        #pragma unroll
        for (int j = 0; j < 8; j++) {
            float t = vm[j];
            t = fmaf(rx, wpv[0][j], t);
            t = fmaf(ry, wpv[1][j], t);
            t = fmaf(rz, wpv[2][j], t);
            t += cbvr[j];
            acc[j] = fmaf(w, t, acc[j]);
        }
    }
    float4 oa = make_float4(acc[0], acc[1], acc[2], acc[3]);
    float4 ob = make_float4(acc[4], acc[5], acc[6], acc[7]);
    float4* op = (float4*)(out + (size_t)n * CH + c0);
    op[0] = oa; op[1] = ob;
}

// ---------------- BN: deterministic two-stage column stats ----------------
__global__ __launch_bounds__(256) void bn_part_kernel(const float* __restrict__ a,
                                                      const float* __restrict__ b) {
    int c = threadIdx.x;
    size_t base = (size_t)blockIdx.x * 256 * CH;
    float s = 0.0f, q = 0.0f;
    for (int r = 0; r < 256; r++) {
        float x = a[base + (size_t)r * CH + c];
        if (b) x += b[base + (size_t)r * CH + c];
        s += x;
        q = fmaf(x, x, q);
    }
    g_ps[blockIdx.x * CH + c] = s;
    g_pq[blockIdx.x * CH + c] = q;
}

__global__ void bn_fin_kernel(const float* __restrict__ g, const float* __restrict__ b) {
    int c = threadIdx.x;
    float s = 0.0f, q = 0.0f;
    for (int blk = 0; blk < 64; blk++) {
        s += g_ps[blk * CH + c];
        q += g_pq[blk * CH + c];
    }
    float m = s * (1.0f / NL);
    float var = q * (1.0f / NL) - m * m;
    float sc = rsqrtf(var + 1e-5f) * g[c];
    g_scale[c] = sc;
    g_shift[c] = b[c] - m * sc;
}

__global__ __launch_bounds__(1024) void bn_apply_kernel(const float* __restrict__ a,
                                                        const float* __restrict__ b,
                                                        float* __restrict__ out) {
    size_t i = (size_t)blockIdx.x * 1024 + threadIdx.x;
    int c = (int)(i & (CH - 1));
    float x = a[i];
    if (b) x += b[i];
    out[i] = fmaf(x, g_scale[c], g_shift[c]);
}

// ---------------- launch ----------------
extern "C" void kernel_launch(void* const* d_in, const int* in_sizes, int n_in,
                              void* d_out, int out_size) {
    const float* lossy_C = (const float*)d_in[0];
    const float* lossy_F = (const float*)d_in[1];
    const float* ref_C   = (const float*)d_in[2];
    const float* ref_F   = (const float*)d_in[3];
    const float* p0w = (const float*)d_in[4];  const float* p0b = (const float*)d_in[5];
    const float* p1w = (const float*)d_in[6];  const float* p1b = (const float*)d_in[7];
    const float* q0w = (const float*)d_in[8];  const float* q0b = (const float*)d_in[9];
    const float* k0w = (const float*)d_in[10]; const float* k0b = (const float*)d_in[11];
    const float* v0w = (const float*)d_in[12]; const float* v0b = (const float*)d_in[13];
    const float* q1w = (const float*)d_in[14]; const float* q1b = (const float*)d_in[15];
    const float* k1w = (const float*)d_in[16]; const float* k1b = (const float*)d_in[17];
    const float* v1w = (const float*)d_in[18]; const float* v1b = (const float*)d_in[19];
    const float* linw = (const float*)d_in[20]; const float* linb = (const float*)d_in[21];
    const float* bn0g = (const float*)d_in[22]; const float* bn0b = (const float*)d_in[23];
    const float* bn1g = (const float*)d_in[24]; const float* bn1b = (const float*)d_in[25];
    float* out = (float*)d_out;

    float *refK0, *refV0, *refK1, *refV1, *Qb, *o0, *o1, *tb, *ub;
    cudaGetSymbolAddress((void**)&refK0, g_refK0);
    cudaGetSymbolAddress((void**)&refV0, g_refV0);
    cudaGetSymbolAddress((void**)&refK1, g_refK1);
    cudaGetSymbolAddress((void**)&refV1, g_refV1);
    cudaGetSymbolAddress((void**)&Qb, g_Q);
    cudaGetSymbolAddress((void**)&o0, g_out0);
    cudaGetSymbolAddress((void**)&o1, g_out1);
    cudaGetSymbolAddress((void**)&tb, g_t);
    cudaGetSymbolAddress((void**)&ub, g_u);

    dim3 ggrid(NL / BM, CH / BN);

    pack_kernel<<<NR / 256, 256>>>(ref_C);
    knn_kernel<<<NL / 64, 256>>>(lossy_C);
    precompute_kernel<<<4, 256>>>(p0w, p0b, p1w, p1b, k0w, k0b, v0w, v0b, k1w, k1b, v1w, v1b);

    gemm_kernel<<<ggrid, 256>>>(ref_F, k0w, nullptr, refK0);
    gemm_kernel<<<ggrid, 256>>>(ref_F, v0w, nullptr, refV0);
    gemm_kernel<<<ggrid, 256>>>(ref_F, k1w, nullptr, refK1);
    gemm_kernel<<<ggrid, 256>>>(ref_F, v1w, nullptr, refV1);

    gemm_kernel<<<ggrid, 256>>>(lossy_F, q0w, q0b, Qb);
    attn_kernel<<<NL / 8, 256>>>(Qb, lossy_C, o0, 0);

    gemm_kernel<<<ggrid, 256>>>(o0, q1w, q1b, Qb);
    attn_kernel<<<NL / 8, 256>>>(Qb, lossy_C, o1, 1);

    // bn0(lossy_F + out) -> t
    bn_part_kernel<<<64, 256>>>(lossy_F, o1);
    bn_fin_kernel<<<1, 256>>>(bn0g, bn0b);
    bn_apply_kernel<<<NL * CH / 1024, 1024>>>(lossy_F, o1, tb);

    // lin
    gemm_kernel<<<ggrid, 256>>>(tb, linw, linb, ub);

    // bn1(u + t) -> out
    bn_part_kernel<<<64, 256>>>(ub, tb);
    bn_fin_kernel<<<1, 256>>>(bn1g, bn1b);
    bn_apply_kernel<<<NL * CH / 1024, 1024>>>(ub, tb, out);
}

// round 13
// speedup vs baseline: 4.2547x; 4.2547x over previous
#include <cuda_runtime.h>
#include <math_constants.h>

#define NL 16384
#define NR 16384
#define CH 256
#define KNN 16

// ---------------- scratch (device globals; no allocation) ----------------
__device__ float4 g_refpack[NR];
__device__ int    g_idx[NL * KNN];
__device__ float  g_refK0[NR * CH];
__device__ float  g_refV0[NR * CH];
__device__ float  g_refK1[NR * CH];
__device__ float  g_refV1[NR * CH];
__device__ float  g_Q[NL * CH];
__device__ float  g_out0[NL * CH];
__device__ float  g_out1[NL * CH];
__device__ float  g_t[NL * CH];
__device__ float  g_u[NL * CH];
__device__ float  g_Wp[4][3][CH];   // pos_w @ {k0,v0,k1,v1}_w
__device__ float  g_cb[4][CH];      // pos_b @ w + b
__device__ float  g_ps[64 * CH];
__device__ float  g_pq[64 * CH];
__device__ float  g_scale[CH];
__device__ float  g_shift[CH];

// ---------------- pack refs: (x,y,z,|r|^2) ----------------
__global__ void pack_kernel(const float* __restrict__ refC) {
    int i = blockIdx.x * 256 + threadIdx.x;
    float x = refC[i * 3 + 0], y = refC[i * 3 + 1], z = refC[i * 3 + 2];
    g_refpack[i] = make_float4(x, y, z, x * x + y * y + z * z);
}

// ---------------- KNN: 64 queries/block, 4 stripes/query ----------------
// Full-ripple insert: single uniform path, all indices static -> arrays stay
// in registers (early-exit variant spilled to local memory: 4.5ms regression).
__device__ __forceinline__ void topk_insert(float (&v)[KNN], int (&id)[KNN], float cv, int ci) {
    v[KNN - 1] = cv; id[KNN - 1] = ci;
    #pragma unroll
    for (int j = KNN - 1; j > 0; --j) {
        if (v[j] < v[j - 1]) {   // strict < keeps ascending-index tie order (matches top_k)
            float tv = v[j]; v[j] = v[j - 1]; v[j - 1] = tv;
            int   ti = id[j]; id[j] = id[j - 1]; id[j - 1] = ti;
        }
    }
}

__global__ __launch_bounds__(256) void knn_kernel(const float* __restrict__ lossyC) {
    __shared__ float4 sm[512];              // phase tile: 512 refs
    __shared__ float  s_val[4][64][KNN];    // per-stripe partial top-16 values
    __shared__ int    s_idx[4][64][KNN];    // per-stripe partial top-16 indices

    const int ql     = threadIdx.x & 63;    // local query 0..63
    const int stripe = threadIdx.x >> 6;    // 0..3
    const int q      = blockIdx.x * 64 + ql;

    const float qx2 = -2.0f * lossyC[q * 3 + 0];
    const float qy2 = -2.0f * lossyC[q * 3 + 1];
    const float qz2 = -2.0f * lossyC[q * 3 + 2];

    float v[KNN]; int id[KNN];
    #pragma unroll
    for (int j = 0; j < KNN; j++) { v[j] = CUDART_INF_F; id[j] = 0; }

    // Stripe s scans [m*512 + s*128, +128) per phase: per-stripe global indices
    // strictly increase across phases -> insertion keeps top_k tie semantics.
    for (int m = 0; m < 32; m++) {
        __syncthreads();
        int base = m * 512;
        sm[threadIdx.x]       = g_refpack[base + threadIdx.x];
        sm[threadIdx.x + 256] = g_refpack[base + threadIdx.x + 256];
        __syncthreads();

        const float4* my = &sm[stripe * 128];
        int gbase = base + stripe * 128;
        for (int r = 0; r < 128; r += 4) {
            float4 a = my[r + 0], b = my[r + 1], c = my[r + 2], d = my[r + 3];
            // val = |r|^2 - 2 q.r : exact fp32 integers -> exact tie semantics
            float c0 = fmaf(a.x, qx2, fmaf(a.y, qy2, fmaf(a.z, qz2, a.w)));
            float c1 = fmaf(b.x, qx2, fmaf(b.y, qy2, fmaf(b.z, qz2, b.w)));
            float c2 = fmaf(c.x, qx2, fmaf(c.y, qy2, fmaf(c.z, qz2, c.w)));
            float c3 = fmaf(d.x, qx2, fmaf(d.y, qy2, fmaf(d.z, qz2, d.w)));
            if (c0 < v[KNN - 1]) topk_insert(v, id, c0, gbase + r + 0);
            if (c1 < v[KNN - 1]) topk_insert(v, id, c1, gbase + r + 1);
            if (c2 < v[KNN - 1]) topk_insert(v, id, c2, gbase + r + 2);
            if (c3 < v[KNN - 1]) topk_insert(v, id, c3, gbase + r + 3);
        }
    }

    #pragma unroll
    for (int j = 0; j < KNN; j++) {
        s_val[stripe][ql][j] = v[j];
        s_idx[stripe][ql][j] = id[j];
    }
    __syncthreads();

    // 4-way merge by (val, idx) lexicographic -> exact top_k order.
    if (threadIdx.x < 64) {
        int p[4] = {0, 0, 0, 0};
        #pragma unroll
        for (int j = 0; j < KNN; j++) {
            float bv = s_val[0][threadIdx.x][p[0]];
            int   bi = s_idx[0][threadIdx.x][p[0]];
            int   bs = 0;
            #pragma unroll
            for (int s = 1; s < 4; s++) {
                float cv = s_val[s][threadIdx.x][p[s]];
                int   ci = s_idx[s][threadIdx.x][p[s]];
                if (cv < bv || (cv == bv && ci < bi)) { bv = cv; bi = ci; bs = s; }
            }
            g_idx[(blockIdx.x * 64 + threadIdx.x) * KNN + j] = bi;
            p[bs]++;
        }
    }
}

// ---------------- tiny precompute: Wp = pos_w @ w, cb = pos_b @ w + b ----------------
__global__ void precompute_kernel(const float* __restrict__ p0w, const float* __restrict__ p0b,
                                  const float* __restrict__ p1w, const float* __restrict__ p1b,
                                  const float* __restrict__ k0w, const float* __restrict__ k0b,
                                  const float* __restrict__ v0w, const float* __restrict__ v0b,
                                  const float* __restrict__ k1w, const float* __restrict__ k1b,
                                  const float* __restrict__ v1w, const float* __restrict__ v1b) {
    int c = threadIdx.x;
    int s = blockIdx.x;
    const float* pw[4] = {p0w, p0w, p1w, p1w};
    const float* pb[4] = {p0b, p0b, p1b, p1b};
    const float* w [4] = {k0w, v0w, k1w, v1w};
    const float* bb[4] = {k0b, v0b, k1b, v1b};
    for (int r = 0; r < 3; r++) {
        float acc = 0.0f;
        for (int m = 0; m < CH; m++) acc = fmaf(pw[s][r * CH + m], w[s][m * CH + c], acc);
        g_Wp[s][r][c] = acc;
    }
    float acc = 0.0f;
    for (int m = 0; m < CH; m++) acc = fmaf(pb[s][m], w[s][m * CH + c], acc);
    g_cb[s][c] = acc + bb[s][c];
}

// ---------------- fp32 SIMT GEMM: C[M,256] = A[M,256] @ B[256,256] (+bias) ----------------
#define BM 128
#define BN 128
#define BK 16
__global__ __launch_bounds__(256) void gemm_kernel(const float* __restrict__ A,
                                                   const float* __restrict__ B,
                                                   const float* __restrict__ bias,
                                                   float* __restrict__ Cout) {
    __shared__ float As[BK][BM + 4];
    __shared__ float Bs[BK][BN];
    const int tid = threadIdx.x;
    const int bm = blockIdx.x * BM;
    const int bn = blockIdx.y * BN;
    const int tx = tid & 15;
    const int ty = tid >> 4;
    float acc[8][8];
    #pragma unroll
    for (int i = 0; i < 8; i++)
        #pragma unroll
        for (int j = 0; j < 8; j++) acc[i][j] = 0.0f;

    for (int kk = 0; kk < CH; kk += BK) {
        #pragma unroll
        for (int u = 0; u < 2; u++) {
            int f = tid + u * 256;
            int row = f >> 2, kq = (f & 3) * 4;
            float4 a4 = *(const float4*)(A + (size_t)(bm + row) * CH + kk + kq);
            As[kq + 0][row] = a4.x; As[kq + 1][row] = a4.y;
            As[kq + 2][row] = a4.z; As[kq + 3][row] = a4.w;
            int kr = f >> 5, col = (f & 31) * 4;
            float4 b4 = *(const float4*)(B + (size_t)(kk + kr) * CH + bn + col);
            *(float4*)(&Bs[kr][col]) = b4;
        }
        __syncthreads();
        #pragma unroll
        for (int k = 0; k < BK; k++) {
            float a[8], b[8];
            *(float4*)(&a[0]) = *(const float4*)(&As[k][ty * 4]);
            *(float4*)(&a[4]) = *(const float4*)(&As[k][ty * 4 + 64]);
            *(float4*)(&b[0]) = *(const float4*)(&Bs[k][tx * 4]);
            *(float4*)(&b[4]) = *(const float4*)(&Bs[k][tx * 4 + 64]);
            #pragma unroll
            for (int i = 0; i < 8; i++)
                #pragma unroll
                for (int j = 0; j < 8; j++)
                    acc[i][j] = fmaf(a[i], b[j], acc[i][j]);
        }
        __syncthreads();
    }
    #pragma unroll
    for (int i = 0; i < 8; i++) {
        int row = bm + ((i < 4) ? (ty * 4 + i) : (64 + ty * 4 + i - 4));
        #pragma unroll
        for (int jh = 0; jh < 2; jh++) {
            int col = bn + jh * 64 + tx * 4;
            float4 o;
            o.x = acc[i][jh * 4 + 0]; o.y = acc[i][jh * 4 + 1];
            o.z = acc[i][jh * 4 + 2]; o.w = acc[i][jh * 4 + 3];
            if (bias) {
                o.x += bias[col + 0]; o.y += bias[col + 1];
                o.z += bias[col + 2]; o.w += bias[col + 3];
            }
            *(float4*)(Cout + (size_t)row * CH + col) = o;
        }
    }
}

// ---------------- attention: one query per warp, float4 gathers ----------------
// lane -> channels c = lane*8 + j, j in 0..7 (two float4 per row per lane)
__global__ __launch_bounds__(256) void attn_kernel(const float* __restrict__ Q,
                                                   const float* __restrict__ lossyC,
                                                   float* __restrict__ out,
                                                   int layer) {
    const float* __restrict__ refK = layer ? g_refK1 : g_refK0;
    const float* __restrict__ refV = layer ? g_refV1 : g_refV0;
    const float* __restrict__ Wpk  = &g_Wp[2 * layer][0][0];
    const float* __restrict__ cbk  = g_cb[2 * layer];
    const float* __restrict__ Wpv  = &g_Wp[2 * layer + 1][0][0];
    const float* __restrict__ cbv  = g_cb[2 * layer + 1];

    const int lane = threadIdx.x & 31;
    const int warp = threadIdx.x >> 5;
    const int n = blockIdx.x * 8 + warp;    // grid = NL/8 = 2048
    const int c0 = lane * 8;

    float wpk[3][8], cbkr[8];
    #pragma unroll
    for (int j = 0; j < 8; j++) {
        #pragma unroll
        for (int r = 0; r < 3; r++) wpk[r][j] = Wpk[r * CH + c0 + j];
        cbkr[j] = cbk[c0 + j];
    }

    const float qx = lossyC[n * 3 + 0], qy = lossyC[n * 3 + 1], qz = lossyC[n * 3 + 2];
    float q[8];
    {
        const float4* qp = (const float4*)(Q + (size_t)n * CH + c0);
        float4 qa = qp[0], qb = qp[1];
        q[0] = qa.x; q[1] = qa.y; q[2] = qa.z; q[3] = qa.w;
        q[4] = qb.x; q[5] = qb.y; q[6] = qb.z; q[7] = qb.w;
    }

    int nb[KNN];
    #pragma unroll
    for (int k = 0; k < KNN; k++) nb[k] = g_idx[n * KNN + k];

    float lgt[KNN];
    #pragma unroll
    for (int k = 0; k < KNN; k++) {
        int i = nb[k];
        float4 rp = g_refpack[i];
        float rx = qx - rp.x, ry = qy - rp.y, rz = qz - rp.z;
        const float4* kp = (const float4*)(refK + (size_t)i * CH + c0);
        float4 ka = kp[0], kb = kp[1];
        float km[8] = {ka.x, ka.y, ka.z, ka.w, kb.x, kb.y, kb.z, kb.w};
        float dot = 0.0f;
        #pragma unroll
        for (int j = 0; j < 8; j++) {
            float t = km[j];
            t = fmaf(rx, wpk[0][j], t);
            t = fmaf(ry, wpk[1][j], t);
            t = fmaf(rz, wpk[2][j], t);
            t += cbkr[j];
            dot = fmaf(t, q[j], dot);
        }
        #pragma unroll
        for (int o = 16; o > 0; o >>= 1) dot += __shfl_xor_sync(0xffffffffu, dot, o);
        lgt[k] = dot * 0.0625f;   // / sqrt(256)
    }
    float mx = lgt[0];
    #pragma unroll
    for (int k = 1; k < KNN; k++) mx = fmaxf(mx, lgt[k]);
    float s = 0.0f;
    #pragma unroll
    for (int k = 0; k < KNN; k++) { float e = __expf(lgt[k] - mx); lgt[k] = e; s += e; }
    float inv = 1.0f / s;

    float wpv[3][8], cbvr[8];
    #pragma unroll
    for (int j = 0; j < 8; j++) {
        #pragma unroll
        for (int r = 0; r < 3; r++) wpv[r][j] = Wpv[r * CH + c0 + j];
        cbvr[j] = cbv[c0 + j];
    }

    float acc[8];
    #pragma unroll
    for (int j = 0; j < 8; j++) acc[j] = 0.0f;
    #pragma unroll
    for (int k = 0; k < KNN; k++) {
        int i = nb[k];
        float4 rp = g_refpack[i];
        float rx = qx - rp.x, ry = qy - rp.y, rz = qz - rp.z;
        float w = lgt[k] * inv;
        const float4* vp = (const float4*)(refV + (size_t)i * CH + c0);
        float4 va = vp[0], vb = vp[1];
        float vm[8] = {va.x, va.y, va.z, va.w, vb.x, vb.y, vb.z, vb.w};
        #pragma unroll
        for (int j = 0; j < 8; j++) {
            float t = vm[j];
            t = fmaf(rx, wpv[0][j], t);
            t = fmaf(ry, wpv[1][j], t);
            t = fmaf(rz, wpv[2][j], t);
            t += cbvr[j];
            acc[j] = fmaf(w, t, acc[j]);
        }
    }
    float4 oa = make_float4(acc[0], acc[1], acc[2], acc[3]);
    float4 ob = make_float4(acc[4], acc[5], acc[6], acc[7]);
    float4* op = (float4*)(out + (size_t)n * CH + c0);
    op[0] = oa; op[1] = ob;
}

// ---------------- BN: deterministic two-stage column stats ----------------
__global__ __launch_bounds__(256) void bn_part_kernel(const float* __restrict__ a,
                                                      const float* __restrict__ b) {
    int c = threadIdx.x;
    size_t base = (size_t)blockIdx.x * 256 * CH;
    float s = 0.0f, q = 0.0f;
    for (int r = 0; r < 256; r++) {
        float x = a[base + (size_t)r * CH + c];
        if (b) x += b[base + (size_t)r * CH + c];
        s += x;
        q = fmaf(x, x, q);
    }
    g_ps[blockIdx.x * CH + c] = s;
    g_pq[blockIdx.x * CH + c] = q;
}

__global__ void bn_fin_kernel(const float* __restrict__ g, const float* __restrict__ b) {
    int c = threadIdx.x;
    float s = 0.0f, q = 0.0f;
    for (int blk = 0; blk < 64; blk++) {
        s += g_ps[blk * CH + c];
        q += g_pq[blk * CH + c];
    }
    float m = s * (1.0f / NL);
    float var = q * (1.0f / NL) - m * m;
    float sc = rsqrtf(var + 1e-5f) * g[c];
    g_scale[c] = sc;
    g_shift[c] = b[c] - m * sc;
}

__global__ __launch_bounds__(1024) void bn_apply_kernel(const float* __restrict__ a,
                                                        const float* __restrict__ b,
                                                        float* __restrict__ out) {
    size_t i = (size_t)blockIdx.x * 1024 + threadIdx.x;
    int c = (int)(i & (CH - 1));
    float x = a[i];
    if (b) x += b[i];
    out[i] = fmaf(x, g_scale[c], g_shift[c]);
}

// ---------------- launch ----------------
extern "C" void kernel_launch(void* const* d_in, const int* in_sizes, int n_in,
                              void* d_out, int out_size) {
    const float* lossy_C = (const float*)d_in[0];
    const float* lossy_F = (const float*)d_in[1];
    const float* ref_C   = (const float*)d_in[2];
    const float* ref_F   = (const float*)d_in[3];
    const float* p0w = (const float*)d_in[4];  const float* p0b = (const float*)d_in[5];
    const float* p1w = (const float*)d_in[6];  const float* p1b = (const float*)d_in[7];
    const float* q0w = (const float*)d_in[8];  const float* q0b = (const float*)d_in[9];
    const float* k0w = (const float*)d_in[10]; const float* k0b = (const float*)d_in[11];
    const float* v0w = (const float*)d_in[12]; const float* v0b = (const float*)d_in[13];
    const float* q1w = (const float*)d_in[14]; const float* q1b = (const float*)d_in[15];
    const float* k1w = (const float*)d_in[16]; const float* k1b = (const float*)d_in[17];
    const float* v1w = (const float*)d_in[18]; const float* v1b = (const float*)d_in[19];
    const float* linw = (const float*)d_in[20]; const float* linb = (const float*)d_in[21];
    const float* bn0g = (const float*)d_in[22]; const float* bn0b = (const float*)d_in[23];
    const float* bn1g = (const float*)d_in[24]; const float* bn1b = (const float*)d_in[25];
    float* out = (float*)d_out;

    float *refK0, *refV0, *refK1, *refV1, *Qb, *o0, *o1, *tb, *ub;
    cudaGetSymbolAddress((void**)&refK0, g_refK0);
    cudaGetSymbolAddress((void**)&refV0, g_refV0);
    cudaGetSymbolAddress((void**)&refK1, g_refK1);
    cudaGetSymbolAddress((void**)&refV1, g_refV1);
    cudaGetSymbolAddress((void**)&Qb, g_Q);
    cudaGetSymbolAddress((void**)&o0, g_out0);
    cudaGetSymbolAddress((void**)&o1, g_out1);
    cudaGetSymbolAddress((void**)&tb, g_t);
    cudaGetSymbolAddress((void**)&ub, g_u);

    dim3 ggrid(NL / BM, CH / BN);

    pack_kernel<<<NR / 256, 256>>>(ref_C);
    knn_kernel<<<NL / 64, 256>>>(lossy_C);
    precompute_kernel<<<4, 256>>>(p0w, p0b, p1w, p1b, k0w, k0b, v0w, v0b, k1w, k1b, v1w, v1b);

    gemm_kernel<<<ggrid, 256>>>(ref_F, k0w, nullptr, refK0);
    gemm_kernel<<<ggrid, 256>>>(ref_F, v0w, nullptr, refV0);
    gemm_kernel<<<ggrid, 256>>>(ref_F, k1w, nullptr, refK1);
    gemm_kernel<<<ggrid, 256>>>(ref_F, v1w, nullptr, refV1);

    gemm_kernel<<<ggrid, 256>>>(lossy_F, q0w, q0b, Qb);
    attn_kernel<<<NL / 8, 256>>>(Qb, lossy_C, o0, 0);

    gemm_kernel<<<ggrid, 256>>>(o0, q1w, q1b, Qb);
    attn_kernel<<<NL / 8, 256>>>(Qb, lossy_C, o1, 1);

    // bn0(lossy_F + out) -> t
    bn_part_kernel<<<64, 256>>>(lossy_F, o1);
    bn_fin_kernel<<<1, 256>>>(bn0g, bn0b);
    bn_apply_kernel<<<NL * CH / 1024, 1024>>>(lossy_F, o1, tb);

    // lin
    gemm_kernel<<<ggrid, 256>>>(tb, linw, linb, ub);

    // bn1(u + t) -> out
    bn_part_kernel<<<64, 256>>>(ub, tb);
    bn_fin_kernel<<<1, 256>>>(bn1g, bn1b);
    bn_apply_kernel<<<NL * CH / 1024, 1024>>>(ub, tb, out);
}

// round 17
// speedup vs baseline: 5.9859x; 1.4069x over previous
#include <cuda_runtime.h>
#include <math_constants.h>

#define NL 16384
#define NR 16384
#define CH 256
#define KNN 16

// ---------------- scratch (device globals; no allocation) ----------------
__device__ float4 g_refpack[NR];
__device__ int    g_idx[NL * KNN];
__device__ float  g_refK0[NR * CH];
__device__ float  g_refV0[NR * CH];
__device__ float  g_refK1[NR * CH];
__device__ float  g_refV1[NR * CH];
__device__ float  g_Q[NL * CH];
__device__ float  g_out0[NL * CH];
__device__ float  g_out1[NL * CH];
__device__ float  g_t[NL * CH];
__device__ float  g_u[NL * CH];
__device__ float  g_Wp[4][3][CH];   // pos_w @ {k0,v0,k1,v1}_w
__device__ float  g_cb[4][CH];      // pos_b @ w + b
__device__ float  g_ps[64 * CH];
__device__ float  g_pq[64 * CH];
__device__ float  g_scale[CH];
__device__ float  g_shift[CH];

// spatial grid for exact KNN
__device__ int    g_cellcnt[4096];
__device__ int    g_cellstart[4097];
__device__ int    g_cellcur[4096];
__device__ float4 g_cellref[NR];    // (x,y,z, idx-as-float-bits), cell-sorted

// ---------------- pack refs: (x,y,z,|r|^2) (attention uses coords) --------
__global__ void pack_kernel(const float* __restrict__ refC) {
    int i = blockIdx.x * 256 + threadIdx.x;
    float x = refC[i * 3 + 0], y = refC[i * 3 + 1], z = refC[i * 3 + 2];
    g_refpack[i] = make_float4(x, y, z, x * x + y * y + z * z);
}

// ---------------- grid build ----------------
__device__ __forceinline__ int cell_of(float x, float y, float z) {
    int cx = min(15, ((int)x) >> 6);
    int cy = min(15, ((int)y) >> 6);
    int cz = min(15, ((int)z) >> 6);
    return (cz * 16 + cy) * 16 + cx;
}

__global__ void grid_zero_kernel() {
    int i = blockIdx.x * 256 + threadIdx.x;
    if (i < 4096) g_cellcnt[i] = 0;
}

__global__ void grid_count_kernel(const float* __restrict__ refC) {
    int i = blockIdx.x * 256 + threadIdx.x;
    atomicAdd(&g_cellcnt[cell_of(refC[3 * i], refC[3 * i + 1], refC[3 * i + 2])], 1);
}

__global__ __launch_bounds__(1024) void grid_scan_kernel() {
    __shared__ int warpsum[32];
    int t = threadIdx.x;
    int c0 = t * 4;
    int s0 = g_cellcnt[c0], s1 = g_cellcnt[c0 + 1], s2 = g_cellcnt[c0 + 2], s3 = g_cellcnt[c0 + 3];
    int e1 = s0, e2 = s0 + s1, e3 = s0 + s1 + s2, tot = e3 + s3;
    int lane = t & 31, warp = t >> 5;
    int x = tot;
    #pragma unroll
    for (int o = 1; o < 32; o <<= 1) { int y = __shfl_up_sync(0xffffffffu, x, o); if (lane >= o) x += y; }
    if (lane == 31) warpsum[warp] = x;
    __syncthreads();
    if (warp == 0) {
        int w = warpsum[lane];
        #pragma unroll
        for (int o = 1; o < 32; o <<= 1) { int y = __shfl_up_sync(0xffffffffu, w, o); if (lane >= o) w += y; }
        warpsum[lane] = w;
    }
    __syncthreads();
    int excl = x - tot + (warp > 0 ? warpsum[warp - 1] : 0);
    g_cellstart[c0] = excl;       g_cellstart[c0 + 1] = excl + e1;
    g_cellstart[c0 + 2] = excl + e2; g_cellstart[c0 + 3] = excl + e3;
    g_cellcur[c0] = excl;         g_cellcur[c0 + 1] = excl + e1;
    g_cellcur[c0 + 2] = excl + e2;   g_cellcur[c0 + 3] = excl + e3;
    if (t == 1023) g_cellstart[4096] = excl + tot;   // == NR
}

__global__ void grid_scatter_kernel(const float* __restrict__ refC) {
    int i = blockIdx.x * 256 + threadIdx.x;
    float x = refC[3 * i], y = refC[3 * i + 1], z = refC[3 * i + 2];
    int c = cell_of(x, y, z);
    int p = atomicAdd(&g_cellcur[c], 1);
    g_cellref[p] = make_float4(x, y, z, __int_as_float(i));
}

// ---------------- grid KNN: thread per query, expanding Chebyshev rings ----
// Keeps the 16 lexicographically-smallest (d2, idx) pairs; scan-order
// independent, so the atomic scatter order is irrelevant. Full-ripple insert
// with static indices only (register-resident; early-exit variant spills).
__device__ __forceinline__ void lex_insert(float (&v)[KNN], int (&id)[KNN], float cv, int ci) {
    v[KNN - 1] = cv; id[KNN - 1] = ci;
    #pragma unroll
    for (int j = KNN - 1; j > 0; --j) {
        bool sw = (v[j] < v[j - 1]) || (v[j] == v[j - 1] && id[j] < id[j - 1]);
        if (sw) {
            float tv = v[j]; v[j] = v[j - 1]; v[j - 1] = tv;
            int   ti = id[j]; id[j] = id[j - 1]; id[j - 1] = ti;
        }
    }
}

__global__ __launch_bounds__(64) void knn_grid_kernel(const float* __restrict__ lossyC) {
    int q = blockIdx.x * 64 + threadIdx.x;
    const float qx = lossyC[3 * q], qy = lossyC[3 * q + 1], qz = lossyC[3 * q + 2];
    const int cx = min(15, ((int)qx) >> 6);
    const int cy = min(15, ((int)qy) >> 6);
    const int cz = min(15, ((int)qz) >> 6);

    float v[KNN]; int id[KNN];
    #pragma unroll
    for (int j = 0; j < KNN; j++) { v[j] = CUDART_INF_F; id[j] = 0x7fffffff; }

    for (int R = 0; R <= 15; R++) {
        int zlo = max(0, cz - R), zhi = min(15, cz + R);
        int ylo = max(0, cy - R), yhi = min(15, cy + R);
        int xlo = max(0, cx - R), xhi = min(15, cx + R);
        for (int z = zlo; z <= zhi; z++) {
            int az = abs(z - cz);
            for (int y = ylo; y <= yhi; y++) {
                int ay = abs(y - cy);
                for (int x = xlo; x <= xhi; x++) {
                    int ch = max(abs(x - cx), max(ay, az));
                    if (ch != R) continue;      // shell only
                    int cell = (z * 16 + y) * 16 + x;
                    int jb = g_cellstart[cell], je = g_cellstart[cell + 1];
                    for (int j = jb; j < je; j++) {
                        float4 rp = g_cellref[j];
                        float dx = qx - rp.x, dy = qy - rp.y, dz = qz - rp.z;
                        // exact integer fp32 (d2 <= 3*1024^2 < 2^24): identical
                        // value to the reference's expanded-form d2
                        float d2 = fmaf(dx, dx, fmaf(dy, dy, dz * dz));
                        int ri = __float_as_int(rp.w);
                        if (d2 < v[KNN - 1] || (d2 == v[KNN - 1] && ri < id[KNN - 1]))
                            lex_insert(v, id, d2, ri);
                    }
                }
            }
        }
        // points in rings > R are at distance >= R*64. Strict < so boundary
        // ties (equal d2, possibly smaller idx outside) force another ring.
        float bound = (float)(R * 64);
        if (v[KNN - 1] < bound * bound) break;
    }

    #pragma unroll
    for (int j = 0; j < KNN; j++) g_idx[q * KNN + j] = id[j];
}

// ---------------- tiny precompute: Wp = pos_w @ w, cb = pos_b @ w + b ----------------
__global__ void precompute_kernel(const float* __restrict__ p0w, const float* __restrict__ p0b,
                                  const float* __restrict__ p1w, const float* __restrict__ p1b,
                                  const float* __restrict__ k0w, const float* __restrict__ k0b,
                                  const float* __restrict__ v0w, const float* __restrict__ v0b,
                                  const float* __restrict__ k1w, const float* __restrict__ k1b,
                                  const float* __restrict__ v1w, const float* __restrict__ v1b) {
    int c = threadIdx.x;
    int s = blockIdx.x;
    const float* pw[4] = {p0w, p0w, p1w, p1w};
    const float* pb[4] = {p0b, p0b, p1b, p1b};
    const float* w [4] = {k0w, v0w, k1w, v1w};
    const float* bb[4] = {k0b, v0b, k1b, v1b};
    for (int r = 0; r < 3; r++) {
        float acc = 0.0f;
        for (int m = 0; m < CH; m++) acc = fmaf(pw[s][r * CH + m], w[s][m * CH + c], acc);
        g_Wp[s][r][c] = acc;
    }
    float acc = 0.0f;
    for (int m = 0; m < CH; m++) acc = fmaf(pb[s][m], w[s][m * CH + c], acc);
    g_cb[s][c] = acc + bb[s][c];
}

// ---------------- fp32 SIMT GEMM: C[M,256] = A[M,256] @ B[256,256] (+bias) ----------------
#define BM 128
#define BN 128
#define BK 16
__global__ __launch_bounds__(256) void gemm_kernel(const float* __restrict__ A,
                                                   const float* __restrict__ B,
                                                   const float* __restrict__ bias,
                                                   float* __restrict__ Cout) {
    __shared__ float As[BK][BM + 4];
    __shared__ float Bs[BK][BN];
    const int tid = threadIdx.x;
    const int bm = blockIdx.x * BM;
    const int bn = blockIdx.y * BN;
    const int tx = tid & 15;
    const int ty = tid >> 4;
    float acc[8][8];
    #pragma unroll
    for (int i = 0; i < 8; i++)
        #pragma unroll
        for (int j = 0; j < 8; j++) acc[i][j] = 0.0f;

    for (int kk = 0; kk < CH; kk += BK) {
        #pragma unroll
        for (int u = 0; u < 2; u++) {
            int f = tid + u * 256;
            int row = f >> 2, kq = (f & 3) * 4;
            float4 a4 = *(const float4*)(A + (size_t)(bm + row) * CH + kk + kq);
            As[kq + 0][row] = a4.x; As[kq + 1][row] = a4.y;
            As[kq + 2][row] = a4.z; As[kq + 3][row] = a4.w;
            int kr = f >> 5, col = (f & 31) * 4;
            float4 b4 = *(const float4*)(B + (size_t)(kk + kr) * CH + bn + col);
            *(float4*)(&Bs[kr][col]) = b4;
        }
        __syncthreads();
        #pragma unroll
        for (int k = 0; k < BK; k++) {
            float a[8], b[8];
            *(float4*)(&a[0]) = *(const float4*)(&As[k][ty * 4]);
            *(float4*)(&a[4]) = *(const float4*)(&As[k][ty * 4 + 64]);
            *(float4*)(&b[0]) = *(const float4*)(&Bs[k][tx * 4]);
            *(float4*)(&b[4]) = *(const float4*)(&Bs[k][tx * 4 + 64]);
            #pragma unroll
            for (int i = 0; i < 8; i++)
                #pragma unroll
                for (int j = 0; j < 8; j++)
                    acc[i][j] = fmaf(a[i], b[j], acc[i][j]);
        }
        __syncthreads();
    }
    #pragma unroll
    for (int i = 0; i < 8; i++) {
        int row = bm + ((i < 4) ? (ty * 4 + i) : (64 + ty * 4 + i - 4));
        #pragma unroll
        for (int jh = 0; jh < 2; jh++) {
            int col = bn + jh * 64 + tx * 4;
            float4 o;
            o.x = acc[i][jh * 4 + 0]; o.y = acc[i][jh * 4 + 1];
            o.z = acc[i][jh * 4 + 2]; o.w = acc[i][jh * 4 + 3];
            if (bias) {
                o.x += bias[col + 0]; o.y += bias[col + 1];
                o.z += bias[col + 2]; o.w += bias[col + 3];
            }
            *(float4*)(Cout + (size_t)row * CH + col) = o;
        }
    }
}

// ---------------- attention: one query per warp, float4 gathers ----------------
// lane -> channels c = lane*8 + j, j in 0..7 (two float4 per row per lane)
__global__ __launch_bounds__(256) void attn_kernel(const float* __restrict__ Q,
                                                   const float* __restrict__ lossyC,
                                                   float* __restrict__ out,
                                                   int layer) {
    const float* __restrict__ refK = layer ? g_refK1 : g_refK0;
    const float* __restrict__ refV = layer ? g_refV1 : g_refV0;
    const float* __restrict__ Wpk  = &g_Wp[2 * layer][0][0];
    const float* __restrict__ cbk  = g_cb[2 * layer];
    const float* __restrict__ Wpv  = &g_Wp[2 * layer + 1][0][0];
    const float* __restrict__ cbv  = g_cb[2 * layer + 1];

    const int lane = threadIdx.x & 31;
    const int warp = threadIdx.x >> 5;
    const int n = blockIdx.x * 8 + warp;    // grid = NL/8 = 2048
    const int c0 = lane * 8;

    float wpk[3][8], cbkr[8];
    #pragma unroll
    for (int j = 0; j < 8; j++) {
        #pragma unroll
        for (int r = 0; r < 3; r++) wpk[r][j] = Wpk[r * CH + c0 + j];
        cbkr[j] = cbk[c0 + j];
    }

    const float qx = lossyC[n * 3 + 0], qy = lossyC[n * 3 + 1], qz = lossyC[n * 3 + 2];
    float q[8];
    {
        const float4* qp = (const float4*)(Q + (size_t)n * CH + c0);
        float4 qa = qp[0], qb = qp[1];
        q[0] = qa.x; q[1] = qa.y; q[2] = qa.z; q[3] = qa.w;
        q[4] = qb.x; q[5] = qb.y; q[6] = qb.z; q[7] = qb.w;
    }

    int nb[KNN];
    #pragma unroll
    for (int k = 0; k < KNN; k++) nb[k] = g_idx[n * KNN + k];

    float lgt[KNN];
    #pragma unroll
    for (int k = 0; k < KNN; k++) {
        int i = nb[k];
        float4 rp = g_refpack[i];
        float rx = qx - rp.x, ry = qy - rp.y, rz = qz - rp.z;
        const float4* kp = (const float4*)(refK + (size_t)i * CH + c0);
        float4 ka = kp[0], kb = kp[1];
        float km[8] = {ka.x, ka.y, ka.z, ka.w, kb.x, kb.y, kb.z, kb.w};
        float dot = 0.0f;
        #pragma unroll
        for (int j = 0; j < 8; j++) {
            float t = km[j];
            t = fmaf(rx, wpk[0][j], t);
            t = fmaf(ry, wpk[1][j], t);
            t = fmaf(rz, wpk[2][j], t);
            t += cbkr[j];
            dot = fmaf(t, q[j], dot);
        }
        #pragma unroll
        for (int o = 16; o > 0; o >>= 1) dot += __shfl_xor_sync(0xffffffffu, dot, o);
        lgt[k] = dot * 0.0625f;   // / sqrt(256)
    }
    float mx = lgt[0];
    #pragma unroll
    for (int k = 1; k < KNN; k++) mx = fmaxf(mx, lgt[k]);
    float s = 0.0f;
    #pragma unroll
    for (int k = 0; k < KNN; k++) { float e = __expf(lgt[k] - mx); lgt[k] = e; s += e; }
    float inv = 1.0f / s;

    float wpv[3][8], cbvr[8];
    #pragma unroll
    for (int j = 0; j < 8; j++) {
        #pragma unroll
        for (int r = 0; r < 3; r++) wpv[r][j] = Wpv[r * CH + c0 + j];
        cbvr[j] = cbv[c0 + j];
    }

    float acc[8];
    #pragma unroll
    for (int j = 0; j < 8; j++) acc[j] = 0.0f;
    #pragma unroll
    for (int k = 0; k < KNN; k++) {
        int i = nb[k];
        float4 rp = g_refpack[i];
        float rx = qx - rp.x, ry = qy - rp.y, rz = qz - rp.z;
        float w = lgt[k] * inv;
        const float4* vp = (const float4*)(refV + (size_t)i * CH + c0);
        float4 va = vp[0], vb = vp[1];
        float vm[8] = {va.x, va.y, va.z, va.w, vb.x, vb.y, vb.z, vb.w};
        #pragma unroll
        for (int j = 0; j < 8; j++) {
            float t = vm[j];
            t = fmaf(rx, wpv[0][j], t);
            t = fmaf(ry, wpv[1][j], t);
            t = fmaf(rz, wpv[2][j], t);
            t += cbvr[j];
            acc[j] = fmaf(w, t, acc[j]);
        }
    }
    float4 oa = make_float4(acc[0], acc[1], acc[2], acc[3]);
    float4 ob = make_float4(acc[4], acc[5], acc[6], acc[7]);
    float4* op = (float4*)(out + (size_t)n * CH + c0);
    op[0] = oa; op[1] = ob;
}

// ---------------- BN: deterministic two-stage column stats ----------------
__global__ __launch_bounds__(256) void bn_part_kernel(const float* __restrict__ a,
                                                      const float* __restrict__ b) {
    int c = threadIdx.x;
    size_t base = (size_t)blockIdx.x * 256 * CH;
    float s = 0.0f, q = 0.0f;
    for (int r = 0; r < 256; r++) {
        float x = a[base + (size_t)r * CH + c];
        if (b) x += b[base + (size_t)r * CH + c];
        s += x;
        q = fmaf(x, x, q);
    }
    g_ps[blockIdx.x * CH + c] = s;
    g_pq[blockIdx.x * CH + c] = q;
}

__global__ void bn_fin_kernel(const float* __restrict__ g, const float* __restrict__ b) {
    int c = threadIdx.x;
    float s = 0.0f, q = 0.0f;
    for (int blk = 0; blk < 64; blk++) {
        s += g_ps[blk * CH + c];
        q += g_pq[blk * CH + c];
    }
    float m = s * (1.0f / NL);
    float var = q * (1.0f / NL) - m * m;
    float sc = rsqrtf(var + 1e-5f) * g[c];
    g_scale[c] = sc;
    g_shift[c] = b[c] - m * sc;
}

__global__ __launch_bounds__(1024) void bn_apply_kernel(const float* __restrict__ a,
                                                        const float* __restrict__ b,
                                                        float* __restrict__ out) {
    size_t i = (size_t)blockIdx.x * 1024 + threadIdx.x;
    int c = (int)(i & (CH - 1));
    float x = a[i];
    if (b) x += b[i];
    out[i] = fmaf(x, g_scale[c], g_shift[c]);
}

// ---------------- launch ----------------
extern "C" void kernel_launch(void* const* d_in, const int* in_sizes, int n_in,
                              void* d_out, int out_size) {
    const float* lossy_C = (const float*)d_in[0];
    const float* lossy_F = (const float*)d_in[1];
    const float* ref_C   = (const float*)d_in[2];
    const float* ref_F   = (const float*)d_in[3];
    const float* p0w = (const float*)d_in[4];  const float* p0b = (const float*)d_in[5];
    const float* p1w = (const float*)d_in[6];  const float* p1b = (const float*)d_in[7];
    const float* q0w = (const float*)d_in[8];  const float* q0b = (const float*)d_in[9];
    const float* k0w = (const float*)d_in[10]; const float* k0b = (const float*)d_in[11];
    const float* v0w = (const float*)d_in[12]; const float* v0b = (const float*)d_in[13];
    const float* q1w = (const float*)d_in[14]; const float* q1b = (const float*)d_in[15];
    const float* k1w = (const float*)d_in[16]; const float* k1b = (const float*)d_in[17];
    const float* v1w = (const float*)d_in[18]; const float* v1b = (const float*)d_in[19];
    const float* linw = (const float*)d_in[20]; const float* linb = (const float*)d_in[21];
    const float* bn0g = (const float*)d_in[22]; const float* bn0b = (const float*)d_in[23];
    const float* bn1g = (const float*)d_in[24]; const float* bn1b = (const float*)d_in[25];
    float* out = (float*)d_out;

    float *refK0, *refV0, *refK1, *refV1, *Qb, *o0, *o1, *tb, *ub;
    cudaGetSymbolAddress((void**)&refK0, g_refK0);
    cudaGetSymbolAddress((void**)&refV0, g_refV0);
    cudaGetSymbolAddress((void**)&refK1, g_refK1);
    cudaGetSymbolAddress((void**)&refV1, g_refV1);
    cudaGetSymbolAddress((void**)&Qb, g_Q);
    cudaGetSymbolAddress((void**)&o0, g_out0);
    cudaGetSymbolAddress((void**)&o1, g_out1);
    cudaGetSymbolAddress((void**)&tb, g_t);
    cudaGetSymbolAddress((void**)&ub, g_u);

    dim3 ggrid(NL / BM, CH / BN);

    pack_kernel<<<NR / 256, 256>>>(ref_C);                  // 1
    grid_zero_kernel<<<16, 256>>>();                        // 2
    grid_count_kernel<<<NR / 256, 256>>>(ref_C);            // 3
    grid_scan_kernel<<<1, 1024>>>();                        // 4
    grid_scatter_kernel<<<NR / 256, 256>>>(ref_C);          // 5
    knn_grid_kernel<<<NL / 64, 64>>>(lossy_C);              // 6 <- ncu profiles this next round
    precompute_kernel<<<4, 256>>>(p0w, p0b, p1w, p1b, k0w, k0b, v0w, v0b, k1w, k1b, v1w, v1b);

    gemm_kernel<<<ggrid, 256>>>(ref_F, k0w, nullptr, refK0);
    gemm_kernel<<<ggrid, 256>>>(ref_F, v0w, nullptr, refV0);
    gemm_kernel<<<ggrid, 256>>>(ref_F, k1w, nullptr, refK1);
    gemm_kernel<<<ggrid, 256>>>(ref_F, v1w, nullptr, refV1);

    gemm_kernel<<<ggrid, 256>>>(lossy_F, q0w, q0b, Qb);
    attn_kernel<<<NL / 8, 256>>>(Qb, lossy_C, o0, 0);

    gemm_kernel<<<ggrid, 256>>>(o0, q1w, q1b, Qb);
    attn_kernel<<<NL / 8, 256>>>(Qb, lossy_C, o1, 1);

    // bn0(lossy_F + out) -> t
    bn_part_kernel<<<64, 256>>>(lossy_F, o1);
    bn_fin_kernel<<<1, 256>>>(bn0g, bn0b);
    bn_apply_kernel<<<NL * CH / 1024, 1024>>>(lossy_F, o1, tb);

    // lin
    gemm_kernel<<<ggrid, 256>>>(tb, linw, linb, ub);

    // bn1(u + t) -> out
    bn_part_kernel<<<64, 256>>>(ub, tb);
    bn_fin_kernel<<<1, 256>>>(bn1g, bn1b);
    bn_apply_kernel<<<NL * CH / 1024, 1024>>>(ub, tb, out);
}